// round 14
// baseline (speedup 1.0000x reference)
#include <cuda_runtime.h>
#include <cuda_fp16.h>
#include <cstdint>

// ---------------------------------------------------------------------------
// Shapes (fixed by the problem instance)
#define B_   8
#define M_   8192
#define D_   1024
#define MB_  2048
#define POS  32
#define KIN  1056
#define ROWS 16384          // B_*MB_
#define KP   1088           // padded GEMM K: 1024 head + 32 ff + 32 zero

// Scratch (device globals; no allocation allowed)
__device__ __align__(256) __half g_A [(size_t)ROWS * KP];  // ~35.7 MB fp16
__device__ __align__(256) __half g_Ws[(size_t)D_   * KP];  //  ~2.2 MB fp16

// ---------------------------------------------------------------------------
// PTX helpers (baseline sm_80/90 features only — compute_103-safe)
// ---------------------------------------------------------------------------
__device__ __forceinline__ uint32_t smem_u32(const void* p) {
    uint32_t a;
    asm("{ .reg .u64 t; cvta.to.shared.u64 t, %1; cvt.u32.u64 %0, t; }" : "=r"(a) : "l"(p));
    return a;
}
#define CP16(dst, src) \
    asm volatile("cp.async.cg.shared.global [%0], [%1], 16;" :: "r"(dst), "l"(src) : "memory")
#define CP_MBAR_ARRIVE_NOINC(a) \
    asm volatile("cp.async.mbarrier.arrive.noinc.shared::cta.b64 [%0];" :: "r"(a) : "memory")
#define MBAR_INIT(a, cnt) \
    asm volatile("mbarrier.init.shared.b64 [%0], %1;" :: "r"(a), "r"(cnt) : "memory")
#define MBAR_ARRIVE(a) \
    asm volatile("mbarrier.arrive.shared::cta.b64 _, [%0];" :: "r"(a) : "memory")
#define MBAR_WAIT(a, ph) do {                                                   \
    uint32_t _m = (a), _p = (ph), _d;                                           \
    asm volatile("{ .reg .pred p; mbarrier.try_wait.parity.acquire.cta.shared::cta.b64 p, [%1], %2; selp.b32 %0,1,0,p; }" \
        : "=r"(_d) : "r"(_m), "r"(_p) : "memory");                              \
    if (!_d) {                                                                  \
        asm volatile("{ .reg .pred P1; WL_%=: mbarrier.try_wait.parity.acquire.cta.shared::cta.b64 P1, [%0], %1, 0x989680; @P1 bra.uni WD_%=; bra.uni WL_%=; WD_%=: }" \
            :: "r"(_m), "r"(_p) : "memory");                                    \
    } } while (0)
#define LDSM4(r0, r1, r2, r3, a) \
    asm volatile("ldmatrix.sync.aligned.m8n8.x4.shared.b16 {%0,%1,%2,%3}, [%4];" \
        : "=r"(r0), "=r"(r1), "=r"(r2), "=r"(r3) : "r"(a))
#define MMA16816(d, a, b) \
    asm volatile("mma.sync.aligned.m16n8k16.row.col.f32.f16.f16.f32 " \
        "{%0,%1,%2,%3}, {%4,%5,%6,%7}, {%8,%9}, {%0,%1,%2,%3};" \
        : "+f"((d)[0]), "+f"((d)[1]), "+f"((d)[2]), "+f"((d)[3]) \
        : "r"((a)[0]), "r"((a)[1]), "r"((a)[2]), "r"((a)[3]), "r"((b)[0]), "r"((b)[1]))

#define SWZ(x) ((x) ^ (((x) >> 3) & 0x70))

__device__ __forceinline__ uint32_t pack2(float a, float b) {
    return (uint32_t)__half_as_ushort(__float2half(a)) |
           ((uint32_t)__half_as_ushort(__float2half(b)) << 16);
}

// ---------------------------------------------------------------------------
// Kernel 1: 4-row mean pool -> fp16 head columns (0..1023), row stride KP.
// ---------------------------------------------------------------------------
__global__ __launch_bounds__(256) void pool_kernel(const float4* __restrict__ in) {
    size_t i = (size_t)blockIdx.x * 256 + threadIdx.x;
    int row = (int)(i >> 8);
    int c4  = (int)(i & 255);
    const float4* p = in + ((size_t)row * 4) * 256 + c4;
    float4 a = p[0], b = p[256], d = p[512], e = p[768];
    uint2 v;
    v.x = pack2(0.25f * (a.x + b.x + d.x + e.x), 0.25f * (a.y + b.y + d.y + e.y));
    v.y = pack2(0.25f * (a.z + b.z + d.z + e.z), 0.25f * (a.w + b.w + d.w + e.w));
    *reinterpret_cast<uint2*>(g_A + (size_t)row * KP + c4 * 4) = v;
}

// ---------------------------------------------------------------------------
// Kernel 1b: fill A tail cols 1024..1087 with [ff(mb) | zeros] for all batches.
// ---------------------------------------------------------------------------
__global__ void ff_fill_kernel() {
    int mb = blockIdx.x;
    int j  = threadIdx.x;            // 0..63
    __half h;
    if (j < 32) {
        float pos  = (float)mb / (float)(MB_ - 1);
        int   f    = j & 15;
        float freq = expf((float)f * (6.907755278982137f / 15.0f));
        float ang  = pos * freq;
        h = __float2half((j < 16) ? sinf(ang) : cosf(ang));
    } else {
        h = __float2half(0.0f);      // zero pad cols 1056..1087
    }
    #pragma unroll
    for (int b = 0; b < B_; ++b)
        g_A[(size_t)(b * MB_ + mb) * KP + 1024 + j] = h;
}

// ---------------------------------------------------------------------------
// Kernel 2: W -> fp16, cols 0..1055 from W, 1056..1087 zero.  grid = D_.
// ---------------------------------------------------------------------------
__global__ __launch_bounds__(160) void wsplit_kernel(const float* __restrict__ W) {
    int o = blockIdx.x;
    int t = threadIdx.x;             // 0..159, active t < 136
    if (t >= 136) return;
    uint4 v;
    if (t < 132) {
        const float* src = W + (size_t)o * KIN + t * 8;
        float4 w0 = *reinterpret_cast<const float4*>(src);
        float4 w1 = *reinterpret_cast<const float4*>(src + 4);
        v.x = pack2(w0.x, w0.y);
        v.y = pack2(w0.z, w0.w);
        v.z = pack2(w1.x, w1.y);
        v.w = pack2(w1.z, w1.w);
    } else {
        v.x = v.y = v.z = v.w = 0;
    }
    *reinterpret_cast<uint4*>(g_Ws + (size_t)o * KP + t * 8) = v;
}

// ---------------------------------------------------------------------------
// Kernel 3: warp-specialized fp16 mma.sync GEMM (mbarrier pipeline).
// C[16384,1024] = A[.,1088] @ Ws[1024,1088]^T + b
// 384 threads: warps 0-7 consumers (64x32 warp tiles, NO cp.async/CP_WAIT/
// syncthreads in loop), warps 8-11 producers (cp.async + arrive.noinc).
// 128x128x64 tiles, 6 stages (192 KB), per-warp elected empty-arrives.
// ---------------------------------------------------------------------------
#define BM 128
#define BN 128
#define BK 64
#define NKC 17               // 1088 / 64
#define STAGES 6
#define TILE_B (BM * BK * 2) // 16 KB (A or B half)
#define STG_B  (2 * TILE_B)  // 32 KB per stage
#define BAR_OFF (STAGES * STG_B)             // 196608
#define SMEM_TOTAL (BAR_OFF + 128)
#define FULL_BAR(s)  (BAR_OFF + (s) * 16)
#define EMPTY_BAR(s) (BAR_OFF + (s) * 16 + 8)

extern __shared__ char dynsmem[];

__global__ __launch_bounds__(384, 1) void gemm_kernel(float* __restrict__ C,
                                                      const float* __restrict__ bias) {
    const uint32_t sb = smem_u32(dynsmem);
    const int tid  = threadIdx.x;
    const int lane = tid & 31;
    const int m0 = blockIdx.y * BM;
    const int n0 = blockIdx.x * BN;

    if (tid == 0) {
        #pragma unroll
        for (int s = 0; s < STAGES; ++s) {
            MBAR_INIT(sb + FULL_BAR(s), 128);   // 128 producer threads (noinc)
            MBAR_INIT(sb + EMPTY_BAR(s), 8);    // 8 consumer warps (elected)
        }
    }
    __syncthreads();

    if (tid >= 256) {
        // ---------------- producers: 128 threads, cp.async ------------------
        const int pt = tid - 256;           // 0..127
        const int prow = pt >> 3;           // 0..15 base row (stride 16)
        const int pseg = pt & 7;
        const __half* gA = g_A  + (size_t)(m0 + prow) * KP + pseg * 8;
        const __half* gB = g_Ws + (size_t)(n0 + prow) * KP + pseg * 8;
        uint32_t pOff[8];
        #pragma unroll
        for (int r = 0; r < 8; ++r)
            pOff[r] = SWZ((uint32_t)((prow + r * 16) * 128 + pseg * 16));

        int s = 0, phase = 1;               // phase 1: first 6 empty-waits pass
        for (int kc = 0; kc < NKC; ++kc) {
            MBAR_WAIT(sb + EMPTY_BAR(s), phase);
            const uint32_t sa = sb + s * STG_B;
            #pragma unroll
            for (int r = 0; r < 8; ++r) {   // A: 128 rows x 64 k
                CP16(sa + pOff[r], gA + (size_t)(r * 16) * KP + kc * 64);
            }
            #pragma unroll
            for (int r = 0; r < 8; ++r) {   // B: 128 rows x 64 k
                CP16(sa + TILE_B + pOff[r], gB + (size_t)(r * 16) * KP + kc * 64);
            }
            CP_MBAR_ARRIVE_NOINC(sb + FULL_BAR(s));
            if (++s == STAGES) { s = 0; phase ^= 1; }
        }
        return;
    }

    // -------------------- consumers: 8 warps, mma --------------------------
    const int wid = tid >> 5;
    const int wm  = wid >> 2;              // 0..1  (M dir, 64 rows)
    const int wn  = wid & 3;               // 0..3  (N dir, 32 cols)

    uint32_t aBase[4], aSwz[4], bBase[2], bSwz[2];
    #pragma unroll
    for (int mt = 0; mt < 4; ++mt) {
        int r = wm * 64 + mt * 16 + (lane & 15);
        aBase[mt] = (uint32_t)(r * 128);
        aSwz[mt]  = (uint32_t)((r & 7) << 4);
    }
    #pragma unroll
    for (int nt2 = 0; nt2 < 2; ++nt2) {
        int r = wn * 32 + nt2 * 16 + (lane & 15);
        bBase[nt2] = (uint32_t)(r * 128);
        bSwz[nt2]  = (uint32_t)((r & 7) << 4);
    }
    const uint32_t hi16 = (lane >> 4) * 16;

    float acc[4][4][4];
    #pragma unroll
    for (int i = 0; i < 4; ++i)
        #pragma unroll
        for (int j = 0; j < 4; ++j)
            #pragma unroll
            for (int v = 0; v < 4; ++v) acc[i][j][v] = 0.0f;

    uint32_t afr[2][4][4], bfr[2][2][4];

    int s = 0, phase = 0;
    for (int kc = 0; kc < NKC; ++kc) {
        MBAR_WAIT(sb + FULL_BAR(s), phase);
        const uint32_t sA = sb + s * STG_B;
        const uint32_t sB = sA + TILE_B;

        // load ks=0 fragments
        {
            const uint32_t kb = hi16;
            #pragma unroll
            for (int mt = 0; mt < 4; ++mt)
                LDSM4(afr[0][mt][0], afr[0][mt][1], afr[0][mt][2], afr[0][mt][3],
                      sA + aBase[mt] + (kb ^ aSwz[mt]));
            #pragma unroll
            for (int nt2 = 0; nt2 < 2; ++nt2)
                LDSM4(bfr[0][nt2][0], bfr[0][nt2][1], bfr[0][nt2][2], bfr[0][nt2][3],
                      sB + bBase[nt2] + (kb ^ bSwz[nt2]));
        }
        #pragma unroll
        for (int ks = 0; ks < 4; ++ks) {
            const int cur = ks & 1, nxt = cur ^ 1;
            if (ks < 3) {
                const uint32_t kb = (ks + 1) * 32 + hi16;
                #pragma unroll
                for (int mt = 0; mt < 4; ++mt)
                    LDSM4(afr[nxt][mt][0], afr[nxt][mt][1], afr[nxt][mt][2], afr[nxt][mt][3],
                          sA + aBase[mt] + (kb ^ aSwz[mt]));
                #pragma unroll
                for (int nt2 = 0; nt2 < 2; ++nt2)
                    LDSM4(bfr[nxt][nt2][0], bfr[nxt][nt2][1], bfr[nxt][nt2][2], bfr[nxt][nt2][3],
                          sB + bBase[nt2] + (kb ^ bSwz[nt2]));
            }
            #pragma unroll
            for (int mt = 0; mt < 4; ++mt) {
                #pragma unroll
                for (int nt = 0; nt < 4; ++nt) {
                    uint32_t bfrag[2] = { bfr[cur][nt >> 1][nt & 1],
                                          bfr[cur][nt >> 1][(nt & 1) + 2] };
                    MMA16816(acc[mt][nt], afr[cur][mt], bfrag);
                }
            }
        }

        // release stage: one elected arrive per consumer warp
        if (lane == 0) MBAR_ARRIVE(sb + EMPTY_BAR(s));
        if (++s == STAGES) { s = 0; phase ^= 1; }
    }

    // ---- epilogue: + bias[col], write C ------------------------------------
    const int group = lane >> 2;
    const int t4    = lane & 3;
    #pragma unroll
    for (int mt = 0; mt < 4; ++mt) {
        #pragma unroll
        for (int half = 0; half < 2; ++half) {
            const int row = m0 + wm * 64 + mt * 16 + group + half * 8;
            float* cp = C + (size_t)row * D_;
            #pragma unroll
            for (int nt = 0; nt < 4; ++nt) {
                const int col = n0 + wn * 32 + nt * 8 + t4 * 2;
                float2 bv = *reinterpret_cast<const float2*>(bias + col);
                float2 v;
                v.x = acc[mt][nt][half * 2]     + bv.x;
                v.y = acc[mt][nt][half * 2 + 1] + bv.y;
                *reinterpret_cast<float2*>(cp + col) = v;
            }
        }
    }
}

// ---------------------------------------------------------------------------
extern "C" void kernel_launch(void* const* d_in, const int* in_sizes, int n_in,
                              void* d_out, int out_size) {
    const float* beat = (const float*)d_in[0];   // [8, 8192, 1024]
    const float* W    = (const float*)d_in[1];   // [1024, 1056]
    const float* bias = (const float*)d_in[2];   // [1024]
    float* out = (float*)d_out;                  // [8, 2048, 1024]

    cudaFuncSetAttribute(gemm_kernel, cudaFuncAttributeMaxDynamicSharedMemorySize,
                         SMEM_TOTAL);

    pool_kernel<<<ROWS, 256>>>((const float4*)beat);
    ff_fill_kernel<<<MB_, 64>>>();
    wsplit_kernel<<<D_, 160>>>(W);
    dim3 grid(D_ / BN, ROWS / BM);               // (8, 128) = 1024 CTAs
    gemm_kernel<<<grid, 384, SMEM_TOTAL>>>(out, bias);
}

// round 15
// speedup vs baseline: 1.0679x; 1.0679x over previous
#include <cuda_runtime.h>
#include <cuda_fp16.h>
#include <cstdint>

// ---------------------------------------------------------------------------
// Shapes (fixed by the problem instance)
#define B_   8
#define M_   8192
#define D_   1024
#define MB_  2048
#define POS  32
#define KIN  1056
#define ROWS 16384          // B_*MB_
#define KP   1088           // padded GEMM K: 1024 head + 32 ff + 32 zero

// Scratch (device globals; no allocation allowed)
__device__ __align__(256) __half g_A [(size_t)ROWS * KP];  // ~35.7 MB fp16
__device__ __align__(256) __half g_Ws[(size_t)D_   * KP];  //  ~2.2 MB fp16
__device__ int g_cnt[128];        // per-mblock pool-completion counters (0..4)

// ---------------------------------------------------------------------------
// PTX helpers (baseline sm_80 features only — compute_103-safe)
// ---------------------------------------------------------------------------
__device__ __forceinline__ uint32_t smem_u32(const void* p) {
    uint32_t a;
    asm("{ .reg .u64 t; cvta.to.shared.u64 t, %1; cvt.u32.u64 %0, t; }" : "=r"(a) : "l"(p));
    return a;
}
#define CP16(dst, src) \
    asm volatile("cp.async.cg.shared.global [%0], [%1], 16;" :: "r"(dst), "l"(src) : "memory")
#define CP_COMMIT() asm volatile("cp.async.commit_group;" ::: "memory")
#define CP_WAIT(n)  asm volatile("cp.async.wait_group %0;" :: "n"(n) : "memory")
#define LDSM4(r0, r1, r2, r3, a) \
    asm volatile("ldmatrix.sync.aligned.m8n8.x4.shared.b16 {%0,%1,%2,%3}, [%4];" \
        : "=r"(r0), "=r"(r1), "=r"(r2), "=r"(r3) : "r"(a))
#define MMA16816(d, a, b) \
    asm volatile("mma.sync.aligned.m16n8k16.row.col.f32.f16.f16.f32 " \
        "{%0,%1,%2,%3}, {%4,%5,%6,%7}, {%8,%9}, {%0,%1,%2,%3};" \
        : "+f"((d)[0]), "+f"((d)[1]), "+f"((d)[2]), "+f"((d)[3]) \
        : "r"((a)[0]), "r"((a)[1]), "r"((a)[2]), "r"((a)[3]), "r"((b)[0]), "r"((b)[1]))

#define SWZ(x) ((x) ^ (((x) >> 3) & 0x70))

__device__ __forceinline__ uint32_t pack2(float a, float b) {
    return (uint32_t)__half_as_ushort(__float2half(a)) |
           ((uint32_t)__half_as_ushort(__float2half(b)) << 16);
}

// ---------------------------------------------------------------------------
// Kernel 1: fill A tail cols 1024..1087 with [ff(mb)|zeros]; block 0 also
// zeroes the pool counters (runs before the fused kernel every replay).
// ---------------------------------------------------------------------------
__global__ void ff_fill_kernel() {
    int mb = blockIdx.x;
    int j  = threadIdx.x;            // 0..63
    if (mb == 0 && j < 64) { g_cnt[j] = 0; g_cnt[j + 64] = 0; }
    __half h;
    if (j < 32) {
        float pos  = (float)mb / (float)(MB_ - 1);
        int   f    = j & 15;
        float freq = expf((float)f * (6.907755278982137f / 15.0f));
        float ang  = pos * freq;
        h = __float2half((j < 16) ? sinf(ang) : cosf(ang));
    } else {
        h = __float2half(0.0f);      // zero pad cols 1056..1087
    }
    #pragma unroll
    for (int b = 0; b < B_; ++b)
        g_A[(size_t)(b * MB_ + mb) * KP + 1024 + j] = h;
}

// ---------------------------------------------------------------------------
// Kernel 2: W -> fp16, cols 0..1055 from W, 1056..1087 zero.  grid = D_.
// ---------------------------------------------------------------------------
__global__ __launch_bounds__(160) void wsplit_kernel(const float* __restrict__ W) {
    int o = blockIdx.x;
    int t = threadIdx.x;             // 0..159, active t < 136
    if (t >= 136) return;
    uint4 v;
    if (t < 132) {
        const float* src = W + (size_t)o * KIN + t * 8;
        float4 w0 = *reinterpret_cast<const float4*>(src);
        float4 w1 = *reinterpret_cast<const float4*>(src + 4);
        v.x = pack2(w0.x, w0.y);
        v.y = pack2(w0.z, w0.w);
        v.z = pack2(w1.x, w1.y);
        v.w = pack2(w1.z, w1.w);
    } else {
        v.x = v.y = v.z = v.w = 0;
    }
    *reinterpret_cast<uint4*>(g_Ws + (size_t)o * KP + t * 8) = v;
}

// ---------------------------------------------------------------------------
// Kernel 3: FUSED persistent pool + fp16 mma.sync GEMM.
// 296 CTAs (2/SM, all resident).  Pool: 512 units x 32 rows; flags per
// 128-row mblock.  GEMM: tiles t = c, c+296, ... of the 128x8 tile grid,
// round-8 pipeline (128x128x64, 3 stages, 8 warps, 64x32 warp tiles).
// Pool HBM traffic overlaps other CTAs' tensor work.
// ---------------------------------------------------------------------------
#define BM 128
#define BN 128
#define BK 64
#define NKC 17               // 1088 / 64
#define NT  1024             // (16384/128) * (1024/128)
#define GRID 296
#define NUNIT 512            // pool units (32 out-rows each)
#define STAGES 3
#define TILE_B (BM * BK * 2) // 16 KB (A or B half)
#define STG_B  (2 * TILE_B)  // 32 KB per stage
#define SMEM_TOTAL (STAGES * STG_B)  // 96 KB

extern __shared__ char dynsmem[];

__device__ __forceinline__ void pool_unit(const float4* __restrict__ in,
                                          int u, int tid) {
    #pragma unroll 4
    for (int i = 0; i < 32; ++i) {
        int idx = i * 256 + tid;
        int row = u * 32 + (idx >> 8);
        int c4  = idx & 255;
        const float4* p = in + ((size_t)row * 4) * 256 + c4;
        float4 a = p[0], b = p[256], d = p[512], e = p[768];
        uint2 v;
        v.x = pack2(0.25f * (a.x + b.x + d.x + e.x), 0.25f * (a.y + b.y + d.y + e.y));
        v.y = pack2(0.25f * (a.z + b.z + d.z + e.z), 0.25f * (a.w + b.w + d.w + e.w));
        *reinterpret_cast<uint2*>(g_A + (size_t)row * KP + c4 * 4) = v;
    }
    __threadfence();
    __syncthreads();                 // all stores fenced before the count
    if (tid == 0) atomicAdd(&g_cnt[u >> 2], 1);
}

__global__ __launch_bounds__(256, 2) void fused_kernel(const float4* __restrict__ in,
                                                       float* __restrict__ C,
                                                       const float* __restrict__ bias) {
    const uint32_t sb = smem_u32(dynsmem);
    const int tid  = threadIdx.x;
    const int lane = tid & 31;
    const int wid  = tid >> 5;
    const int wm   = wid >> 2;          // 0..1  (M dir, 64 rows)
    const int wn   = wid & 3;           // 0..3  (N dir, 32 cols)
    const int c    = blockIdx.x;

    const int grow = tid >> 3;          // 0..31 base row (stride 32)
    const int gseg = tid & 7;           // 16B segment within 128B row

    uint32_t ldOff[4];
    #pragma unroll
    for (int r = 0; r < 4; ++r)
        ldOff[r] = SWZ((uint32_t)((grow + r * 32) * 128 + gseg * 16));

    uint32_t aBase[4], aSwz[4], bBase[2], bSwz[2];
    #pragma unroll
    for (int mt = 0; mt < 4; ++mt) {
        int r = wm * 64 + mt * 16 + (lane & 15);
        aBase[mt] = (uint32_t)(r * 128);
        aSwz[mt]  = (uint32_t)((r & 7) << 4);
    }
    #pragma unroll
    for (int nt2 = 0; nt2 < 2; ++nt2) {
        int r = wn * 32 + nt2 * 16 + (lane & 15);
        bBase[nt2] = (uint32_t)(r * 128);
        bSwz[nt2]  = (uint32_t)((r & 7) << 4);
    }
    const uint32_t hi16 = (lane >> 4) * 16;

    // ---- pool first unit ----------------------------------------------------
    pool_unit(in, c, tid);              // c < 296 < NUNIT always

    // ---- tile rounds, with second pool unit interleaved ---------------------
    for (int round = 0, t = c; t < NT; ++round, t += GRID) {
        if (round == 1 && c + GRID < NUNIT)
            pool_unit(in, c + GRID, tid);

        const int mb = t >> 3;
        const int m0 = mb << 7;
        const int n0 = (t & 7) << 7;

        // wait for this tile's A rows to be pooled
        if (tid == 0) {
            int v;
            do {
                asm volatile("ld.acquire.gpu.global.b32 %0, [%1];"
                             : "=r"(v) : "l"(g_cnt + mb) : "memory");
            } while (v < 4);
        }
        __syncthreads();

        const __half* gA = g_A  + (size_t)(m0 + grow) * KP + gseg * 8;
        const __half* gB = g_Ws + (size_t)(n0 + grow) * KP + gseg * 8;

        float acc[4][4][4];
        #pragma unroll
        for (int i = 0; i < 4; ++i)
            #pragma unroll
            for (int j = 0; j < 4; ++j)
                #pragma unroll
                for (int v = 0; v < 4; ++v) acc[i][j][v] = 0.0f;

        // prologue: prefetch 2 chunks
        #pragma unroll
        for (int s = 0; s < STAGES - 1; ++s) {
            const uint32_t sa = sb + s * STG_B;
            #pragma unroll
            for (int r = 0; r < 4; ++r) {
                CP16(sa + ldOff[r],          gA + (size_t)(r * 32) * KP + s * 64);
                CP16(sa + TILE_B + ldOff[r], gB + (size_t)(r * 32) * KP + s * 64);
            }
            CP_COMMIT();
        }

        uint32_t afr[2][4][4], bfr[2][2][4];

        for (int kc = 0; kc < NKC; ++kc) {
            CP_WAIT(STAGES - 2);
            __syncthreads();

            const int kn = kc + STAGES - 1;
            if (kn < NKC) {
                const uint32_t sa = sb + (kn % STAGES) * STG_B;
                #pragma unroll
                for (int r = 0; r < 4; ++r) {
                    CP16(sa + ldOff[r],          gA + (size_t)(r * 32) * KP + kn * 64);
                    CP16(sa + TILE_B + ldOff[r], gB + (size_t)(r * 32) * KP + kn * 64);
                }
            }
            CP_COMMIT();

            const uint32_t sA = sb + (kc % STAGES) * STG_B;
            const uint32_t sB = sA + TILE_B;

            {
                const uint32_t kb = hi16;
                #pragma unroll
                for (int mt = 0; mt < 4; ++mt)
                    LDSM4(afr[0][mt][0], afr[0][mt][1], afr[0][mt][2], afr[0][mt][3],
                          sA + aBase[mt] + (kb ^ aSwz[mt]));
                #pragma unroll
                for (int nt2 = 0; nt2 < 2; ++nt2)
                    LDSM4(bfr[0][nt2][0], bfr[0][nt2][1], bfr[0][nt2][2], bfr[0][nt2][3],
                          sB + bBase[nt2] + (kb ^ bSwz[nt2]));
            }
            #pragma unroll
            for (int ks = 0; ks < 4; ++ks) {
                const int cur = ks & 1, nxt = cur ^ 1;
                if (ks < 3) {
                    const uint32_t kb = (ks + 1) * 32 + hi16;
                    #pragma unroll
                    for (int mt = 0; mt < 4; ++mt)
                        LDSM4(afr[nxt][mt][0], afr[nxt][mt][1], afr[nxt][mt][2], afr[nxt][mt][3],
                              sA + aBase[mt] + (kb ^ aSwz[mt]));
                    #pragma unroll
                    for (int nt2 = 0; nt2 < 2; ++nt2)
                        LDSM4(bfr[nxt][nt2][0], bfr[nxt][nt2][1], bfr[nxt][nt2][2], bfr[nxt][nt2][3],
                              sB + bBase[nt2] + (kb ^ bSwz[nt2]));
                }
                #pragma unroll
                for (int mt = 0; mt < 4; ++mt) {
                    #pragma unroll
                    for (int nt = 0; nt < 4; ++nt) {
                        uint32_t bfrag[2] = { bfr[cur][nt >> 1][nt & 1],
                                              bfr[cur][nt >> 1][(nt & 1) + 2] };
                        MMA16816(acc[mt][nt], afr[cur][mt], bfrag);
                    }
                }
            }
        }

        // epilogue: + bias[col], write C
        const int group = lane >> 2;
        const int t4    = lane & 3;
        #pragma unroll
        for (int mt = 0; mt < 4; ++mt) {
            #pragma unroll
            for (int half = 0; half < 2; ++half) {
                const int row = m0 + wm * 64 + mt * 16 + group + half * 8;
                float* cp = C + (size_t)row * D_;
                #pragma unroll
                for (int nt = 0; nt < 4; ++nt) {
                    const int col = n0 + wn * 32 + nt * 8 + t4 * 2;
                    float2 bv = *reinterpret_cast<const float2*>(bias + col);
                    float2 v;
                    v.x = acc[mt][nt][half * 2]     + bv.x;
                    v.y = acc[mt][nt][half * 2 + 1] + bv.y;
                    *reinterpret_cast<float2*>(cp + col) = v;
                }
            }
        }
        __syncthreads();   // smem stages reused next tile
    }
}

// ---------------------------------------------------------------------------
extern "C" void kernel_launch(void* const* d_in, const int* in_sizes, int n_in,
                              void* d_out, int out_size) {
    const float* beat = (const float*)d_in[0];   // [8, 8192, 1024]
    const float* W    = (const float*)d_in[1];   // [1024, 1056]
    const float* bias = (const float*)d_in[2];   // [1024]
    float* out = (float*)d_out;                  // [8, 2048, 1024]

    cudaFuncSetAttribute(fused_kernel, cudaFuncAttributeMaxDynamicSharedMemorySize,
                         SMEM_TOTAL);

    ff_fill_kernel<<<MB_, 64>>>();               // also zeroes g_cnt
    wsplit_kernel<<<D_, 160>>>(W);
    fused_kernel<<<GRID, 256, SMEM_TOTAL>>>((const float4*)beat, out, bias);
}